// round 5
// baseline (speedup 1.0000x reference)
#include <cuda_runtime.h>

// ---------------- problem constants ----------------
#define BB    16
#define CIN   4
#define DIN   64
#define C1    24
#define D1    34
#define C2    16
#define D2    19
#define PAD   5
#define TAPS  343

#define D1SQ  (D1*D1)
#define D1CU  (D1*D1*D1)
#define D2SQ  (D2*D2)
#define D2CU  (D2*D2*D2)

// conv1: tile 9x9x9, 256 threads (243 active), V=3 z-voxels/thread
#define S1N   23
#define IN1_N (S1N*S1N*S1N)      // 12167
#define W1_ELEMS (TAPS*C1)       // 8232
#define CONV1_SMEM (IN1_N*4)     // 48668 B

// conv2: tile 5x5x10, 128 threads (125 active), V=2 z-voxels/thread
#define S2XN  15
#define S2ZN  25
#define VCH_N (S2XN*S2XN*S2ZN)   // 5625
#define VCH_PADN 5632
#define CONV2_SMEM (3*VCH_PADN*4)  // 67584 B

#define Y_ELEMS (BB*C2*D2CU)     // 1755904

// ---------------- scratch ----------------
__device__ float  g_v[(size_t)BB*C1*D1CU];
__device__ float  g_y[(size_t)Y_ELEMS];
__device__ float  g_K1[CIN*TAPS*C1];           // [ci][tap][co]
__device__ float  g_K2[8*7*49*9*C2];           // [u][kz][kyx][ic9][co]
__device__ double g_sum[C2], g_sumsq[C2];
__device__ float  g_coef[2*C2];

// ---------------- packed f32x2 helpers ----------------
__device__ __forceinline__ void ffma2(unsigned long long &d,
                                      unsigned long long a,
                                      unsigned long long b) {
    asm("fma.rn.f32x2 %0, %1, %2, %0;" : "+l"(d) : "l"(a), "l"(b));
}
__device__ __forceinline__ unsigned long long mul2(unsigned long long a,
                                                   unsigned long long b) {
    unsigned long long r;
    asm("mul.rn.f32x2 %0, %1, %2;" : "=l"(r) : "l"(a), "l"(b));
    return r;
}
__device__ __forceinline__ unsigned long long splat2(float v) {
    unsigned long long r;
    unsigned int u = __float_as_uint(v);
    asm("mov.b64 %0, {%1, %1};" : "=l"(r) : "r"(u));
    return r;
}
__device__ __forceinline__ float2 unpack2(unsigned long long p) {
    unsigned int lo, hi;
    asm("mov.b64 {%0, %1}, %2;" : "=r"(lo), "=r"(hi) : "l"(p));
    return make_float2(__uint_as_float(lo), __uint_as_float(hi));
}

// ---------------- small kernels ----------------
__global__ void zero_y_kernel() {
    int idx = blockIdx.x * 256 + threadIdx.x;   // exactly Y_ELEMS
    g_y[idx] = 0.f;
    if (idx < C2) { g_sum[idx] = 0.0; g_sumsq[idx] = 0.0; }
}

__global__ void gen_K1_kernel(const float* __restrict__ W1,
                              const float* __restrict__ basis1) {
    int idx = blockIdx.x * 256 + threadIdx.x;
    if (idx >= CIN*TAPS*C1) return;
    int co = idx % C1;
    int r  = idx / C1;
    int tap = r % TAPS;
    int ci  = r / TAPS;
    int u = co / 3, i = co % 3;
    float s = 0.f;
#pragma unroll
    for (int b = 0; b < 3; b++)
        s += W1[(u*CIN + ci)*3 + b] * basis1[(b*3 + i)*TAPS + tap];
    g_K1[idx] = s;
}

__global__ void gen_K2_kernel(const float* __restrict__ W2a,
                              const float* __restrict__ basis2a,
                              const float* __restrict__ W2b,
                              const float* __restrict__ basis2b) {
    int idx = blockIdx.x * 256 + threadIdx.x;
    if (idx >= 8*7*49*9*C2) return;
    int co = idx & 15;
    int r  = idx >> 4;
    int ic = r % 9;  r /= 9;
    int kyx = r % 49; r /= 49;
    int kz = r % 7;
    int u  = r / 7;
    int tap = kz*49 + kyx;
    float s = 0.f;
    if (ic < 3) {
#pragma unroll
        for (int b = 0; b < 3; b++)
            s += W2a[(co*8 + u)*3 + b] * basis2a[(b*3 + ic)*TAPS + tap];
    } else {
        const int I[6] = {0,0,0,1,1,2};
        const int J[6] = {0,1,2,1,2,2};
        int i = I[ic-3], j = J[ic-3];
#pragma unroll
        for (int b = 0; b < 3; b++) {
            float w  = W2b[(co*8 + u)*3 + b];
            float bs = basis2b[(b*9 + i*3 + j)*TAPS + tap];
            if (i != j) bs += basis2b[(b*9 + j*3 + i)*TAPS + tap];
            s += w * bs;
        }
    }
    g_K2[idx] = s;
}

// ---------------- conv1: s[16,4,64^3] -> v[16,24,34^3] ----------------
__global__ __launch_bounds__(256, 2)
void conv1_kernel(const float* __restrict__ s) {
    extern __shared__ float smi[];   // IN1_N

    int tid = threadIdx.x;
    int b  = blockIdx.z >> 2;
    int tz = blockIdx.z & 3;
    int ox0 = blockIdx.x * 9, oy0 = blockIdx.y * 9, oz0 = tz * 9;
    int ix0 = 2*ox0 - PAD, iy0 = 2*oy0 - PAD, iz0 = 2*oz0 - PAD;

    int lx = tid % 9;
    int rr = tid / 9;
    int ly = rr % 9;
    int lz3 = rr / 9;
    bool live = (lz3 < 3);
    int lz = live ? lz3 : 0;

    unsigned long long acc[36];
#pragma unroll
    for (int q = 0; q < 36; q++) acc[q] = 0ULL;

    for (int ci = 0; ci < CIN; ci++) {
        __syncthreads();
        {
            const float* sp = s + ((size_t)b*CIN + ci) * (DIN*DIN*DIN);
            for (int t = tid; t < IN1_N; t += 256) {
                int dx = t % S1N;
                int r  = t / S1N;
                int dy = r % S1N;
                int dz = r / S1N;
                int ix = ix0 + dx, iy = iy0 + dy, iz = iz0 + dz;
                float v = 0.f;
                if ((unsigned)ix < DIN && (unsigned)iy < DIN && (unsigned)iz < DIN)
                    v = sp[((size_t)iz*DIN + iy)*DIN + ix];
                smi[t] = v;
            }
        }
        __syncthreads();

        const ulonglong2* wci = (const ulonglong2*)(g_K1 + ci*W1_ELEMS);
        int zb = 6*lz, yb = 2*ly, xb = 2*lx;
#pragma unroll 1
        for (int kz = 0; kz < 7; kz++) {
#pragma unroll 1
            for (int ky = 0; ky < 7; ky++) {
                const float* r0 = &smi[(zb+kz)*(S1N*S1N) + (yb+ky)*S1N + xb];
                const ulonglong2* wrow = wci + (kz*7 + ky)*42;   // 7*24 floats
#pragma unroll
                for (int kx = 0; kx < 7; kx++) {
                    unsigned long long a0 = splat2(r0[kx]);
                    unsigned long long a1 = splat2(r0[kx + 2*S1N*S1N]);
                    unsigned long long a2 = splat2(r0[kx + 4*S1N*S1N]);
                    const ulonglong2* wp = wrow + kx*6;          // 24 floats
#pragma unroll
                    for (int q = 0; q < 6; q++) {
                        ulonglong2 w = __ldg(wp + q);
                        ffma2(acc[2*q],      a0, w.x);
                        ffma2(acc[2*q+1],    a0, w.y);
                        ffma2(acc[12+2*q],   a1, w.x);
                        ffma2(acc[12+2*q+1], a1, w.y);
                        ffma2(acc[24+2*q],   a2, w.x);
                        ffma2(acc[24+2*q+1], a2, w.y);
                    }
                }
            }
        }
    }

    int ox = ox0 + lx, oy = oy0 + ly;
    if (live && ox < D1 && oy < D1) {
#pragma unroll
        for (int k = 0; k < 3; k++) {
            int oz = oz0 + 3*lz + k;
            if (oz < D1) {
                size_t base = ((size_t)b*C1)*D1CU + (size_t)oz*D1SQ + oy*D1 + ox;
#pragma unroll
                for (int q = 0; q < 12; q++) {
                    float2 f = unpack2(acc[k*12 + q]);
                    g_v[base + (size_t)(2*q)  *D1CU] = f.x;
                    g_v[base + (size_t)(2*q+1)*D1CU] = f.y;
                }
            }
        }
    }
}

// ------- conv2 (+ fused tensor product), u-split x4, atomic y -------
__global__ __launch_bounds__(128, 3)
void conv2_kernel() {
    extern __shared__ float sv[];    // 3 * VCH_PADN

    int tid = threadIdx.x;
    int bz = blockIdx.z;             // (b, tz, usplit)
    int us = bz & 3;
    int tz = (bz >> 2) & 1;
    int b  = bz >> 3;
    int ox0 = blockIdx.x * 5, oy0 = blockIdx.y * 5, oz0 = tz * 10;
    int ix0 = 2*ox0 - PAD, iy0 = 2*oy0 - PAD, iz0 = 2*oz0 - PAD;

    int lx = tid % 5;
    int rr = tid / 5;
    int ly = rr % 5;
    int lz5 = rr / 5;
    bool live = (lz5 < 5);
    int lz = live ? lz5 : 0;

    unsigned long long acc[16];
#pragma unroll
    for (int q = 0; q < 16; q++) acc[q] = 0ULL;

    for (int uu = 0; uu < 2; uu++) {
        int u = us*2 + uu;
        __syncthreads();
        for (int c = 0; c < 3; c++) {
            const float* vp = g_v + ((size_t)b*C1 + u*3 + c) * D1CU;
            for (int t = tid; t < VCH_N; t += 128) {
                int dx = t % S2XN;
                int r  = t / S2XN;
                int dy = r % S2XN;
                int dz = r / S2XN;
                int ix = ix0 + dx, iy = iy0 + dy, iz = iz0 + dz;
                float val = 0.f;
                if ((unsigned)ix < D1 && (unsigned)iy < D1 && (unsigned)iz < D1)
                    val = vp[((size_t)iz*D1 + iy)*D1 + ix];
                sv[c*VCH_PADN + dz*(S2XN*S2XN) + dy*S2XN + dx] = val;
            }
        }
        __syncthreads();

#pragma unroll 1
        for (int kz = 0; kz < 7; kz++) {
            int z0 = 2*lz + kz;
            const float* p0 = &sv[z0*(S2XN*S2XN) + (2*ly)*S2XN + 2*lx];
            const ulonglong2* wkz =
                (const ulonglong2*)(g_K2 + (size_t)((u*7 + kz)*49)*(9*C2));
#pragma unroll 1
            for (int ky = 0; ky < 7; ky++) {
#pragma unroll 1
                for (int kx = 0; kx < 7; kx++) {
                    int off = ky*S2XN + kx;
                    unsigned long long s00 = splat2(p0[off]);
                    unsigned long long s01 = splat2(p0[off + VCH_PADN]);
                    unsigned long long s02 = splat2(p0[off + 2*VCH_PADN]);
                    unsigned long long s10 = splat2(p0[off + 10*S2XN*S2XN]);
                    unsigned long long s11 = splat2(p0[off + 10*S2XN*S2XN + VCH_PADN]);
                    unsigned long long s12 = splat2(p0[off + 10*S2XN*S2XN + 2*VCH_PADN]);
                    unsigned long long pk0[9], pk1[9];
                    pk0[0] = s00; pk0[1] = s01; pk0[2] = s02;
                    pk0[3] = mul2(s00, s00);
                    pk0[4] = mul2(s00, s01);
                    pk0[5] = mul2(s00, s02);
                    pk0[6] = mul2(s01, s01);
                    pk0[7] = mul2(s01, s02);
                    pk0[8] = mul2(s02, s02);
                    pk1[0] = s10; pk1[1] = s11; pk1[2] = s12;
                    pk1[3] = mul2(s10, s10);
                    pk1[4] = mul2(s10, s11);
                    pk1[5] = mul2(s10, s12);
                    pk1[6] = mul2(s11, s11);
                    pk1[7] = mul2(s11, s12);
                    pk1[8] = mul2(s12, s12);
                    // 9*C2 = 144 floats per tap = 36 ulonglong2
                    const ulonglong2* wp = wkz + (ky*7 + kx)*36;
#pragma unroll
                    for (int ic = 0; ic < 9; ic++) {
                        ulonglong2 w0 = __ldg(wp + ic*4 + 0);
                        ulonglong2 w1 = __ldg(wp + ic*4 + 1);
                        ulonglong2 w2 = __ldg(wp + ic*4 + 2);
                        ulonglong2 w3 = __ldg(wp + ic*4 + 3);
                        ffma2(acc[0], pk0[ic], w0.x);
                        ffma2(acc[1], pk0[ic], w0.y);
                        ffma2(acc[2], pk0[ic], w1.x);
                        ffma2(acc[3], pk0[ic], w1.y);
                        ffma2(acc[4], pk0[ic], w2.x);
                        ffma2(acc[5], pk0[ic], w2.y);
                        ffma2(acc[6], pk0[ic], w3.x);
                        ffma2(acc[7], pk0[ic], w3.y);
                        ffma2(acc[8],  pk1[ic], w0.x);
                        ffma2(acc[9],  pk1[ic], w0.y);
                        ffma2(acc[10], pk1[ic], w1.x);
                        ffma2(acc[11], pk1[ic], w1.y);
                        ffma2(acc[12], pk1[ic], w2.x);
                        ffma2(acc[13], pk1[ic], w2.y);
                        ffma2(acc[14], pk1[ic], w3.x);
                        ffma2(acc[15], pk1[ic], w3.y);
                    }
                }
            }
        }
    }

    int ox = ox0 + lx, oy = oy0 + ly;
#pragma unroll
    for (int v = 0; v < 2; v++) {
        int oz = oz0 + lz + 5*v;
        if (live && ox < D2 && oy < D2 && oz < D2) {
            size_t base = ((size_t)b*C2)*D2CU + (size_t)oz*D2SQ + oy*D2 + ox;
#pragma unroll
            for (int q = 0; q < 8; q++) {
                float2 f = unpack2(acc[v*8 + q]);
                atomicAdd(&g_y[base + (size_t)(2*q)  *D2CU], f.x);
                atomicAdd(&g_y[base + (size_t)(2*q+1)*D2CU], f.y);
            }
        }
    }
}

// ---------------- BN stats: reduce g_y ----------------
__global__ void stats_kernel() {
    __shared__ float red[2*8];
    int c = blockIdx.x;
    int b = blockIdx.y;
    const float* p = g_y + ((size_t)b*C2 + c)*D2CU;
    float s1 = 0.f, s2 = 0.f;
    for (int i = threadIdx.x; i < D2CU; i += 256) {
        float v = p[i];
        s1 += v; s2 += v*v;
    }
    int lane = threadIdx.x & 31, wid = threadIdx.x >> 5;
#pragma unroll
    for (int o = 16; o > 0; o >>= 1) {
        s1 += __shfl_down_sync(0xffffffffu, s1, o);
        s2 += __shfl_down_sync(0xffffffffu, s2, o);
    }
    if (lane == 0) { red[wid] = s1; red[8 + wid] = s2; }
    __syncthreads();
    if (threadIdx.x == 0) {
        float t1 = 0.f, t2 = 0.f;
#pragma unroll
        for (int w = 0; w < 8; w++) { t1 += red[w]; t2 += red[8 + w]; }
        atomicAdd(&g_sum[c],   (double)t1);
        atomicAdd(&g_sumsq[c], (double)t2);
    }
}

// ---------------- BN coefficients ----------------
__global__ void coef_kernel(const float* __restrict__ gamma,
                            const float* __restrict__ beta,
                            const float* __restrict__ bias) {
    int c = threadIdx.x;
    if (c < C2) {
        double N = (double)BB * (double)D2CU;
        double mean = g_sum[c] / N;
        double var  = g_sumsq[c] / N - mean*mean;
        float a = gamma[c] * rsqrtf((float)var + 1e-5f);
        g_coef[c]       = a;
        g_coef[C2 + c]  = beta[c] - a * (float)mean + bias[c];
    }
}

// ---------------- BN apply + bias + relu ----------------
__global__ void apply_kernel(float* __restrict__ out) {
    int idx = blockIdx.x * 256 + threadIdx.x;   // exactly Y_ELEMS
    int c = (idx / D2CU) & 15;
    float a = g_coef[c], b = g_coef[C2 + c];
    out[idx] = fmaxf(fmaf(a, g_y[idx], b), 0.f);
}

// ---------------- launch ----------------
extern "C" void kernel_launch(void* const* d_in, const int* in_sizes, int n_in,
                              void* d_out, int out_size) {
    (void)in_sizes; (void)n_in; (void)out_size;
    const float* s       = (const float*)d_in[0];
    const float* basis1  = (const float*)d_in[1];
    const float* W1      = (const float*)d_in[2];
    const float* basis2a = (const float*)d_in[3];
    const float* basis2b = (const float*)d_in[4];
    const float* W2a     = (const float*)d_in[5];
    const float* W2b     = (const float*)d_in[6];
    const float* gamma   = (const float*)d_in[7];
    const float* beta    = (const float*)d_in[8];
    const float* bias    = (const float*)d_in[9];
    float* out = (float*)d_out;

    cudaFuncSetAttribute(conv1_kernel,
        cudaFuncAttributeMaxDynamicSharedMemorySize, CONV1_SMEM);
    cudaFuncSetAttribute(conv2_kernel,
        cudaFuncAttributeMaxDynamicSharedMemorySize, CONV2_SMEM);

    zero_y_kernel<<<Y_ELEMS/256, 256>>>();
    gen_K1_kernel<<<(CIN*TAPS*C1 + 255)/256, 256>>>(W1, basis1);
    gen_K2_kernel<<<(8*7*49*9*C2 + 255)/256, 256>>>(W2a, basis2a, W2b, basis2b);
    conv1_kernel<<<dim3(4, 4, BB*4), 256, CONV1_SMEM>>>(s);
    conv2_kernel<<<dim3(4, 4, BB*8), 128, CONV2_SMEM>>>();
    stats_kernel<<<dim3(C2, BB), 256>>>();
    coef_kernel<<<1, C2>>>(gamma, beta, bias);
    apply_kernel<<<Y_ELEMS/256, 256>>>(out);
}

// round 6
// speedup vs baseline: 1.6728x; 1.6728x over previous
#include <cuda_runtime.h>

// ---------------- problem constants ----------------
#define BB    16
#define CIN   4
#define DIN   64
#define C1    24
#define D1    34
#define C2    16
#define D2    19
#define PAD   5
#define TAPS  343

#define D1SQ  (D1*D1)
#define D1CU  (D1*D1*D1)
#define D2SQ  (D2*D2)
#define D2CU  (D2*D2*D2)

// conv1: tile 9x9x9, 256 threads (243 active), V=3 z-voxels/thread, smem weights
#define S1N   23
#define IN1_N (S1N*S1N*S1N)      // 12167
#define W1_ELEMS (TAPS*C1)       // 8232
#define CONV1_SMEM ((W1_ELEMS + IN1_N)*4)   // 81596 B

// conv2: kz-split. tile 5x5x19 outputs, 256 threads (250 active), V=2 in z.
// For fixed kz only even-offset input planes are touched -> 19 compressed planes.
#define PLN   227                // 15*15=225 padded to odd 227 (bank spread)
#define CSTR  (19*PLN)           // 4313
#define CPAD  4320               // channel stride, padded
#define W2_SLICE (49*9*C2)       // 7056 floats per (u,kz)
#define CONV2_SMEM ((3*CPAD + W2_SLICE)*4)   // 80064 B

#define Y_ELEMS (BB*C2*D2CU)     // 1755904 = 6859*256

// ---------------- scratch ----------------
__device__ float  g_v[(size_t)BB*C1*D1CU];
__device__ float  g_y[(size_t)Y_ELEMS];
__device__ float  g_K1[CIN*TAPS*C1];           // [ci][tap][co]
__device__ float  g_K2[8*7*49*9*C2];           // [u][kz][kyx][ic9][co]
__device__ double g_sum[C2], g_sumsq[C2];
__device__ float  g_coef[2*C2];

// ---------------- packed f32x2 helpers ----------------
__device__ __forceinline__ void ffma2(unsigned long long &d,
                                      unsigned long long a,
                                      unsigned long long b) {
    asm("fma.rn.f32x2 %0, %1, %2, %0;" : "+l"(d) : "l"(a), "l"(b));
}
__device__ __forceinline__ unsigned long long mul2(unsigned long long a,
                                                   unsigned long long b) {
    unsigned long long r;
    asm("mul.rn.f32x2 %0, %1, %2;" : "=l"(r) : "l"(a), "l"(b));
    return r;
}
__device__ __forceinline__ unsigned long long splat2(float v) {
    unsigned long long r;
    unsigned int u = __float_as_uint(v);
    asm("mov.b64 %0, {%1, %1};" : "=l"(r) : "r"(u));
    return r;
}
__device__ __forceinline__ float2 unpack2(unsigned long long p) {
    unsigned int lo, hi;
    asm("mov.b64 {%0, %1}, %2;" : "=r"(lo), "=r"(hi) : "l"(p));
    return make_float2(__uint_as_float(lo), __uint_as_float(hi));
}

// ---------------- small kernels ----------------
__global__ void zero_y_kernel() {
    int idx = blockIdx.x * 256 + threadIdx.x;   // exactly Y_ELEMS
    g_y[idx] = 0.f;
    if (idx < C2) { g_sum[idx] = 0.0; g_sumsq[idx] = 0.0; }
}

__global__ void gen_K1_kernel(const float* __restrict__ W1,
                              const float* __restrict__ basis1) {
    int idx = blockIdx.x * 256 + threadIdx.x;
    if (idx >= CIN*TAPS*C1) return;
    int co = idx % C1;
    int r  = idx / C1;
    int tap = r % TAPS;
    int ci  = r / TAPS;
    int u = co / 3, i = co % 3;
    float s = 0.f;
#pragma unroll
    for (int b = 0; b < 3; b++)
        s += W1[(u*CIN + ci)*3 + b] * basis1[(b*3 + i)*TAPS + tap];
    g_K1[idx] = s;
}

__global__ void gen_K2_kernel(const float* __restrict__ W2a,
                              const float* __restrict__ basis2a,
                              const float* __restrict__ W2b,
                              const float* __restrict__ basis2b) {
    int idx = blockIdx.x * 256 + threadIdx.x;
    if (idx >= 8*7*49*9*C2) return;
    int co = idx & 15;
    int r  = idx >> 4;
    int ic = r % 9;  r /= 9;
    int kyx = r % 49; r /= 49;
    int kz = r % 7;
    int u  = r / 7;
    int tap = kz*49 + kyx;
    float s = 0.f;
    if (ic < 3) {
#pragma unroll
        for (int b = 0; b < 3; b++)
            s += W2a[(co*8 + u)*3 + b] * basis2a[(b*3 + ic)*TAPS + tap];
    } else {
        const int I[6] = {0,0,0,1,1,2};
        const int J[6] = {0,1,2,1,2,2};
        int i = I[ic-3], j = J[ic-3];
#pragma unroll
        for (int b = 0; b < 3; b++) {
            float w  = W2b[(co*8 + u)*3 + b];
            float bs = basis2b[(b*9 + i*3 + j)*TAPS + tap];
            if (i != j) bs += basis2b[(b*9 + j*3 + i)*TAPS + tap];
            s += w * bs;
        }
    }
    g_K2[idx] = s;
}

// ---------------- conv1: s[16,4,64^3] -> v[16,24,34^3] (round-2 design) ----
__global__ __launch_bounds__(256, 2)
void conv1_kernel(const float* __restrict__ s) {
    extern __shared__ float sm[];
    float* smw = sm;                 // W1_ELEMS
    float* smi = sm + W1_ELEMS;      // IN1_N

    int tid = threadIdx.x;
    int b  = blockIdx.z >> 2;
    int tz = blockIdx.z & 3;
    int ox0 = blockIdx.x * 9, oy0 = blockIdx.y * 9, oz0 = tz * 9;
    int ix0 = 2*ox0 - PAD, iy0 = 2*oy0 - PAD, iz0 = 2*oz0 - PAD;

    int lx = tid % 9;
    int rr = tid / 9;
    int ly = rr % 9;
    int lz3 = rr / 9;
    bool live = (lz3 < 3);
    int lz = live ? lz3 : 0;

    unsigned long long acc[36];
#pragma unroll
    for (int q = 0; q < 36; q++) acc[q] = 0ULL;

    for (int ci = 0; ci < CIN; ci++) {
        __syncthreads();
        {   // stage weights (vectorized)
            const float4* src = (const float4*)(g_K1 + ci*W1_ELEMS);
            float4* dst = (float4*)smw;
            for (int t = tid; t < W1_ELEMS/4; t += 256) dst[t] = src[t];
        }
        {   // stage input tile with zero padding
            const float* sp = s + ((size_t)b*CIN + ci) * (DIN*DIN*DIN);
            for (int t = tid; t < IN1_N; t += 256) {
                int dx = t % S1N;
                int r  = t / S1N;
                int dy = r % S1N;
                int dz = r / S1N;
                int ix = ix0 + dx, iy = iy0 + dy, iz = iz0 + dz;
                float v = 0.f;
                if ((unsigned)ix < DIN && (unsigned)iy < DIN && (unsigned)iz < DIN)
                    v = sp[((size_t)iz*DIN + iy)*DIN + ix];
                smi[t] = v;
            }
        }
        __syncthreads();

        int zb = 6*lz, yb = 2*ly, xb = 2*lx;
#pragma unroll 1
        for (int kz = 0; kz < 7; kz++) {
#pragma unroll 1
            for (int ky = 0; ky < 7; ky++) {
                const float* r0 = &smi[(zb+kz)*(S1N*S1N) + (yb+ky)*S1N + xb];
                const ulonglong2* wrow =
                    (const ulonglong2*)&smw[(kz*7 + ky)*7*C1];
#pragma unroll
                for (int kx = 0; kx < 7; kx++) {
                    unsigned long long a0 = splat2(r0[kx]);
                    unsigned long long a1 = splat2(r0[kx + 2*S1N*S1N]);
                    unsigned long long a2 = splat2(r0[kx + 4*S1N*S1N]);
                    const ulonglong2* wp = wrow + kx*6;
#pragma unroll
                    for (int q = 0; q < 6; q++) {
                        ulonglong2 w = wp[q];
                        ffma2(acc[2*q],      a0, w.x);
                        ffma2(acc[2*q+1],    a0, w.y);
                        ffma2(acc[12+2*q],   a1, w.x);
                        ffma2(acc[12+2*q+1], a1, w.y);
                        ffma2(acc[24+2*q],   a2, w.x);
                        ffma2(acc[24+2*q+1], a2, w.y);
                    }
                }
            }
        }
    }

    int ox = ox0 + lx, oy = oy0 + ly;
    if (live && ox < D1 && oy < D1) {
#pragma unroll
        for (int k = 0; k < 3; k++) {
            int oz = oz0 + 3*lz + k;
            if (oz < D1) {
                size_t base = ((size_t)b*C1)*D1CU + (size_t)oz*D1SQ + oy*D1 + ox;
#pragma unroll
                for (int q = 0; q < 12; q++) {
                    float2 f = unpack2(acc[k*12 + q]);
                    g_v[base + (size_t)(2*q)  *D1CU] = f.x;
                    g_v[base + (size_t)(2*q+1)*D1CU] = f.y;
                }
            }
        }
    }
}

// ------- conv2: kz-split, fused tensor product, atomic y -------
// grid: (4, 4, 16*7*2); block handles all 19 z outputs for ONE kz, 4 u-groups.
__global__ __launch_bounds__(256, 2)
void conv2_kernel() {
    extern __shared__ float sm[];
    float* sv  = sm;                 // 3 * CPAD (compressed z-planes)
    float* smw = sm + 3*CPAD;        // W2_SLICE

    int tid = threadIdx.x;
    int bz = blockIdx.z;             // (b, kz, usplit)
    int us = bz & 1;
    int kz = (bz >> 1) % 7;
    int b  = bz / 14;
    int ox0 = blockIdx.x * 5, oy0 = blockIdx.y * 5;

    int lx = tid % 5;
    int rr = tid / 5;
    int ly = rr % 5;
    int lz10 = rr / 5;               // 0..10 (250..255 -> 10)
    bool live = (lz10 < 10);
    int lz = live ? lz10 : 0;

    unsigned long long acc[16];      // [v 0..1][8 channel-pairs]
#pragma unroll
    for (int q = 0; q < 16; q++) acc[q] = 0ULL;

    for (int uu = 0; uu < 4; uu++) {
        int u = us*4 + uu;
        __syncthreads();
        {   // stage weights for (u, kz): 7056 floats
            const float4* src = (const float4*)(g_K2 + (size_t)(u*7 + kz)*W2_SLICE);
            float4* dst = (float4*)smw;
            for (int t = tid; t < W2_SLICE/4; t += 256) dst[t] = src[t];
        }
        // stage 3 channels, 19 compressed planes of 15x15
        for (int c = 0; c < 3; c++) {
            const float* vp = g_v + ((size_t)b*C1 + u*3 + c) * D1CU;
            for (int t = tid; t < 19*225; t += 256) {
                int xl = t % 15;
                int r2 = t / 15;
                int yl = r2 % 15;
                int p  = r2 / 15;                 // output z plane
                int ix = 2*ox0 - 5 + xl;
                int iy = 2*oy0 - 5 + yl;
                int iz = 2*p + kz - 5;
                float val = 0.f;
                if ((unsigned)ix < D1 && (unsigned)iy < D1 && (unsigned)iz < D1)
                    val = vp[((size_t)iz)*D1SQ + iy*D1 + ix];
                sv[c*CPAD + p*PLN + yl*15 + xl] = val;
            }
        }
        __syncthreads();

        const float* p0 = &sv[lz*PLN + (2*ly)*15 + 2*lx];
        const int IA[9] = {0,1,2,0,0,0,1,1,2};
        const int JA[9] = {0,1,2,0,1,2,1,2,2};
#pragma unroll 1
        for (int ky = 0; ky < 7; ky++) {
#pragma unroll 1
            for (int kx = 0; kx < 7; kx++) {
                int off = ky*15 + kx;
                unsigned long long s0[3], s1[3];
                s0[0] = splat2(p0[off]);
                s0[1] = splat2(p0[off + CPAD]);
                s0[2] = splat2(p0[off + 2*CPAD]);
                s1[0] = splat2(p0[off + 10*PLN]);
                s1[1] = splat2(p0[off + 10*PLN + CPAD]);
                s1[2] = splat2(p0[off + 10*PLN + 2*CPAD]);
                const ulonglong2* wp =
                    (const ulonglong2*)&smw[(ky*7 + kx)*(9*C2)];
#pragma unroll
                for (int ic = 0; ic < 9; ic++) {
                    unsigned long long pk0, pk1;
                    if (ic < 3) { pk0 = s0[ic]; pk1 = s1[ic]; }
                    else {
                        pk0 = mul2(s0[IA[ic]], s0[JA[ic]]);
                        pk1 = mul2(s1[IA[ic]], s1[JA[ic]]);
                    }
                    ulonglong2 w0 = wp[ic*4+0];
                    ulonglong2 w1 = wp[ic*4+1];
                    ulonglong2 w2 = wp[ic*4+2];
                    ulonglong2 w3 = wp[ic*4+3];
                    ffma2(acc[0], pk0, w0.x);
                    ffma2(acc[1], pk0, w0.y);
                    ffma2(acc[2], pk0, w1.x);
                    ffma2(acc[3], pk0, w1.y);
                    ffma2(acc[4], pk0, w2.x);
                    ffma2(acc[5], pk0, w2.y);
                    ffma2(acc[6], pk0, w3.x);
                    ffma2(acc[7], pk0, w3.y);
                    ffma2(acc[8],  pk1, w0.x);
                    ffma2(acc[9],  pk1, w0.y);
                    ffma2(acc[10], pk1, w1.x);
                    ffma2(acc[11], pk1, w1.y);
                    ffma2(acc[12], pk1, w2.x);
                    ffma2(acc[13], pk1, w2.y);
                    ffma2(acc[14], pk1, w3.x);
                    ffma2(acc[15], pk1, w3.y);
                }
            }
        }
    }

    int ox = ox0 + lx, oy = oy0 + ly;
#pragma unroll
    for (int v = 0; v < 2; v++) {
        int oz = lz + 10*v;
        if (live && ox < D2 && oy < D2 && oz < D2) {
            size_t base = ((size_t)b*C2)*D2CU + (size_t)oz*D2SQ + oy*D2 + ox;
#pragma unroll
            for (int q = 0; q < 8; q++) {
                float2 f = unpack2(acc[v*8 + q]);
                atomicAdd(&g_y[base + (size_t)(2*q)  *D2CU], f.x);
                atomicAdd(&g_y[base + (size_t)(2*q+1)*D2CU], f.y);
            }
        }
    }
}

// ---------------- BN stats: reduce g_y ----------------
__global__ void stats_kernel() {
    __shared__ float red[2*8];
    int c = blockIdx.x;
    int b = blockIdx.y;
    const float* p = g_y + ((size_t)b*C2 + c)*D2CU;
    float s1 = 0.f, s2 = 0.f;
    for (int i = threadIdx.x; i < D2CU; i += 256) {
        float v = p[i];
        s1 += v; s2 += v*v;
    }
    int lane = threadIdx.x & 31, wid = threadIdx.x >> 5;
#pragma unroll
    for (int o = 16; o > 0; o >>= 1) {
        s1 += __shfl_down_sync(0xffffffffu, s1, o);
        s2 += __shfl_down_sync(0xffffffffu, s2, o);
    }
    if (lane == 0) { red[wid] = s1; red[8 + wid] = s2; }
    __syncthreads();
    if (threadIdx.x == 0) {
        float t1 = 0.f, t2 = 0.f;
#pragma unroll
        for (int w = 0; w < 8; w++) { t1 += red[w]; t2 += red[8 + w]; }
        atomicAdd(&g_sum[c],   (double)t1);
        atomicAdd(&g_sumsq[c], (double)t2);
    }
}

// ---------------- BN coefficients ----------------
__global__ void coef_kernel(const float* __restrict__ gamma,
                            const float* __restrict__ beta,
                            const float* __restrict__ bias) {
    int c = threadIdx.x;
    if (c < C2) {
        double N = (double)BB * (double)D2CU;
        double mean = g_sum[c] / N;
        double var  = g_sumsq[c] / N - mean*mean;
        float a = gamma[c] * rsqrtf((float)var + 1e-5f);
        g_coef[c]       = a;
        g_coef[C2 + c]  = beta[c] - a * (float)mean + bias[c];
    }
}

// ---------------- BN apply + bias + relu ----------------
__global__ void apply_kernel(float* __restrict__ out) {
    int idx = blockIdx.x * 256 + threadIdx.x;   // exactly Y_ELEMS
    int c = (idx / D2CU) & 15;
    float a = g_coef[c], b = g_coef[C2 + c];
    out[idx] = fmaxf(fmaf(a, g_y[idx], b), 0.f);
}

// ---------------- launch ----------------
extern "C" void kernel_launch(void* const* d_in, const int* in_sizes, int n_in,
                              void* d_out, int out_size) {
    (void)in_sizes; (void)n_in; (void)out_size;
    const float* s       = (const float*)d_in[0];
    const float* basis1  = (const float*)d_in[1];
    const float* W1      = (const float*)d_in[2];
    const float* basis2a = (const float*)d_in[3];
    const float* basis2b = (const float*)d_in[4];
    const float* W2a     = (const float*)d_in[5];
    const float* W2b     = (const float*)d_in[6];
    const float* gamma   = (const float*)d_in[7];
    const float* beta    = (const float*)d_in[8];
    const float* bias    = (const float*)d_in[9];
    float* out = (float*)d_out;

    cudaFuncSetAttribute(conv1_kernel,
        cudaFuncAttributeMaxDynamicSharedMemorySize, CONV1_SMEM);
    cudaFuncSetAttribute(conv2_kernel,
        cudaFuncAttributeMaxDynamicSharedMemorySize, CONV2_SMEM);

    zero_y_kernel<<<Y_ELEMS/256, 256>>>();
    gen_K1_kernel<<<(CIN*TAPS*C1 + 255)/256, 256>>>(W1, basis1);
    gen_K2_kernel<<<(8*7*49*9*C2 + 255)/256, 256>>>(W2a, basis2a, W2b, basis2b);
    conv1_kernel<<<dim3(4, 4, BB*4), 256, CONV1_SMEM>>>(s);
    conv2_kernel<<<dim3(4, 4, BB*7*2), 256, CONV2_SMEM>>>();
    stats_kernel<<<dim3(C2, BB), 256>>>();
    coef_kernel<<<1, C2>>>(gamma, beta, bias);
    apply_kernel<<<Y_ELEMS/256, 256>>>(out);
}

// round 8
// speedup vs baseline: 3.1142x; 1.8617x over previous
#include <cuda_runtime.h>

#define BB    16
#define CIN   4
#define DIN   64
#define D1    34
#define D2    19
#define TAPS  343
#define D1SQ  1156
#define D1CU  39304
#define D2SQ  361
#define D2CU  6859
#define D2P   6860            // padded channel stride for m (even, for float2)
#define NSLOT 36
#define MSLOT 48
#define Y_ELEMS (BB*16*D2CU)  // 1755904 = 6859*256
#define M_ELEMS (BB*MSLOT*D2P) // 5268480 = 20580*256

typedef unsigned long long ull;

// K1: tile 9x9x12 out, 256 thr (243 live), 4 z-voxels/thread, 5 ch-pairs
#define K1_W   1715           // 343 taps * 5 ull (packed channel pairs)
#define K1_IN  15341          // 23*23*29 floats
#define K1_SMEM (K1_W*8 + K1_IN*4)   // 75084 B

// K3: kz-split, tile 5x5x19 out via 10 packed z-slots, 256 thr (250 live)
#define PLNU  227             // 15*15=225 padded (ull units)
#define CSTU  (10*PLNU)       // 2270 ull per channel
#define K3W   (49*28)         // 1372 ull weights per kz (27 used + pad)
#define K3_SMEM ((3*CSTU + K3W)*8)   // 65456 B

// ---------------- scratch ----------------
__device__ float  g_n[(size_t)BB*NSLOT*D1CU];   // 90.6 MB
__device__ float  g_v[(size_t)BB*24*D1CU];      // 60.4 MB
__device__ float  g_m[(size_t)M_ELEMS + 8];     // 21.1 MB (+pad)
__device__ float  g_y[(size_t)Y_ELEMS];
__device__ ull    g_B1[K1_W];
__device__ ull    g_B2[7*K3W];
__device__ ull    g_W1s[NSLOT*8];
__device__ ull    g_W2s[MSLOT*16];
__device__ double g_sum[16], g_sumsq[16];
__device__ float  g_coef[32];

// ---------------- f32x2 helpers ----------------
__device__ __forceinline__ void ffma2(ull &d, ull a, ull b) {
    asm("fma.rn.f32x2 %0, %1, %2, %0;" : "+l"(d) : "l"(a), "l"(b));
}
__device__ __forceinline__ ull mul2(ull a, ull b) {
    ull r; asm("mul.rn.f32x2 %0, %1, %2;" : "=l"(r) : "l"(a), "l"(b)); return r;
}
__device__ __forceinline__ ull splat2(float v) {
    ull r; unsigned u = __float_as_uint(v);
    asm("mov.b64 %0, {%1, %1};" : "=l"(r) : "r"(u)); return r;
}
__device__ __forceinline__ ull pack2(float lo, float hi) {
    ull r; unsigned a = __float_as_uint(lo), b = __float_as_uint(hi);
    asm("mov.b64 %0, {%1, %2};" : "=l"(r) : "r"(a), "r"(b)); return r;
}
__device__ __forceinline__ float2 unpack2(ull p) {
    unsigned lo, hi;
    asm("mov.b64 {%0, %1}, %2;" : "=r"(lo), "=r"(hi) : "l"(p));
    return make_float2(__uint_as_float(lo), __uint_as_float(hi));
}

// ---------------- setup kernels ----------------
__global__ void zero_m_kernel() {
    int idx = blockIdx.x * 256 + threadIdx.x;   // exactly M_ELEMS
    g_m[idx] = 0.f;
    if (idx < 16) { g_sum[idx] = 0.0; g_sumsq[idx] = 0.0; }
    if (idx >= M_ELEMS - 8 && idx < M_ELEMS) g_m[idx + 8] = 0.f; // pad
}

// B1[tap*5+p] = pair (basis1[2p], basis1[2p+1]) ; channel c = b*3+i
__global__ void gen_B1_kernel(const float* __restrict__ basis1) {
    int idx = blockIdx.x * 256 + threadIdx.x;
    if (idx >= K1_W) return;
    int tap = idx / 5, p = idx % 5;
    float w0 = basis1[(2*p)*TAPS + tap];
    float w1 = (2*p + 1 < 9) ? basis1[(2*p+1)*TAPS + tap] : 0.f;
    g_B1[idx] = pack2(w0, w1);
}

// B2[kz][kyx][e] splatted ; e<9: a-part [b3][i] ; 9..26: folded b-part [b3][ic6]
__global__ void gen_B2_kernel(const float* __restrict__ b2a,
                              const float* __restrict__ b2b) {
    int idx = blockIdx.x * 256 + threadIdx.x;
    if (idx >= 7*K3W) return;
    int kz = idx / K3W;
    int r  = idx % K3W;
    int kyx = r / 28, e = r % 28;
    int tap = kz*49 + kyx;
    float w = 0.f;
    if (e < 9) {
        int b3 = e / 3, i = e % 3;
        w = b2a[(b3*3 + i)*TAPS + tap];
    } else if (e < 27) {
        const int IA[6] = {0,0,0,1,1,2};
        const int JA[6] = {0,1,2,1,2,2};
        int e2 = e - 9;
        int b3 = e2 / 6, ic = e2 % 6;
        int i = IA[ic], j = JA[ic];
        w = b2b[(b3*9 + i*3 + j)*TAPS + tap];
        if (i != j) w += b2b[(b3*9 + j*3 + i)*TAPS + tap];
    }
    g_B2[idx] = pack2(w, w);
}

// W1s[slot*8+u] = splat(W1[u][ci][b]) ; slot = ci*9 + b*3 + i
__global__ void gen_W1s_kernel(const float* __restrict__ W1) {
    int idx = blockIdx.x * 256 + threadIdx.x;
    if (idx >= NSLOT*8) return;
    int sl = idx / 8, u = idx % 8;
    int ci = sl / 9, c = sl % 9, b = c / 3;
    g_W1s[idx] = splat2(W1[(u*CIN + ci)*3 + b]);
}

// W2s[s*16+co] = splat(W2x[co][u][b3]) ; s = u*6 + j (j<3: a, else b)
__global__ void gen_W2s_kernel(const float* __restrict__ W2a,
                               const float* __restrict__ W2b) {
    int idx = blockIdx.x * 256 + threadIdx.x;
    if (idx >= MSLOT*16) return;
    int s = idx / 16, co = idx % 16;
    int u = s / 6, j = s % 6;
    float w = (j < 3) ? W2a[(co*8 + u)*3 + j] : W2b[(co*8 + u)*3 + (j-3)];
    g_W2s[idx] = splat2(w);
}

// ---------------- K1: basis conv1, s[16,4,64^3] -> n[16,36,34^3] ----------
__global__ __launch_bounds__(256, 2)
void k1_kernel(const float* __restrict__ s) {
    extern __shared__ char smraw[];
    ull*   smw = (ull*)smraw;                 // K1_W
    float* smi = (float*)(smraw + K1_W*8);    // K1_IN

    int tid = threadIdx.x;
    int b  = blockIdx.z / 3;
    int zt = blockIdx.z % 3;
    int ox0 = blockIdx.x * 9, oy0 = blockIdx.y * 9, oz0 = zt * 12;
    int ix0 = 2*ox0 - 5, iy0 = 2*oy0 - 5, iz0 = 2*oz0 - 5;

    int lx = tid % 9;
    int rr = tid / 9;
    int ly = rr % 9;
    int lz3 = rr / 9;
    bool live = (lz3 < 3);
    int lz = live ? lz3 : 0;

    for (int t = tid; t < K1_W; t += 256) smw[t] = g_B1[t];

    for (int ci = 0; ci < CIN; ci++) {
        __syncthreads();
        {
            const float* sp = s + ((size_t)b*CIN + ci) * (DIN*DIN*DIN);
            for (int t = tid; t < K1_IN; t += 256) {
                int dx = t % 23;
                int r  = t / 23;
                int dy = r % 23;
                int dz = r / 23;
                int ix = ix0 + dx, iy = iy0 + dy, iz = iz0 + dz;
                float v = 0.f;
                if ((unsigned)ix < DIN && (unsigned)iy < DIN && (unsigned)iz < DIN)
                    v = sp[((size_t)iz*DIN + iy)*DIN + ix];
                smi[t] = v;
            }
        }
        __syncthreads();

        ull acc[20];
#pragma unroll
        for (int q = 0; q < 20; q++) acc[q] = 0ULL;

#pragma unroll 1
        for (int kz = 0; kz < 7; kz++) {
#pragma unroll 1
            for (int ky = 0; ky < 7; ky++) {
                const float* r0 = &smi[(2*lz + kz)*529 + (2*ly + ky)*23 + 2*lx];
                const ull* wrow = &smw[(kz*7 + ky)*35];
#pragma unroll
                for (int kx = 0; kx < 7; kx++) {
                    ull w0 = wrow[kx*5+0], w1 = wrow[kx*5+1], w2 = wrow[kx*5+2];
                    ull w3 = wrow[kx*5+3], w4 = wrow[kx*5+4];
#pragma unroll
                    for (int k = 0; k < 4; k++) {
                        ull a = splat2(r0[kx + k*3174]);   // z plane +6k
                        ffma2(acc[k],    a, w0);
                        ffma2(acc[4+k],  a, w1);
                        ffma2(acc[8+k],  a, w2);
                        ffma2(acc[12+k], a, w3);
                        ffma2(acc[16+k], a, w4);
                    }
                }
            }
        }

        int ox = ox0 + lx, oy = oy0 + ly;
        if (live && ox < D1 && oy < D1) {
#pragma unroll
            for (int k = 0; k < 4; k++) {
                int oz = oz0 + lz + 3*k;
                if (oz < D1) {
                    size_t base = ((size_t)b*NSLOT + ci*9)*D1CU
                                + (size_t)oz*D1SQ + oy*D1 + ox;
#pragma unroll
                    for (int p = 0; p < 5; p++) {
                        float2 f = unpack2(acc[p*4 + k]);
                        g_n[base + (size_t)(2*p)*D1CU] = f.x;
                        if (p < 4) g_n[base + (size_t)(2*p+1)*D1CU] = f.y;
                    }
                }
            }
        }
    }
}

// ---------------- C1: combine n -> v[16,24,34^3] ----------------
__global__ void c1_kernel() {
    __shared__ ull tw[NSLOT*8];
    int tid = threadIdx.x;
    for (int t = tid; t < NSLOT*8; t += 256) tw[t] = g_W1s[t];
    __syncthreads();
    size_t idx = (size_t)blockIdx.x * 256 + tid;
    if (idx >= (size_t)BB * (D1CU/2)) return;
    int b  = (int)(idx / (D1CU/2));
    int t2 = (int)(idx % (D1CU/2));

    const float2* np = (const float2*)(g_n + (size_t)b*NSLOT*D1CU) + t2;
    ull acc[24];
#pragma unroll
    for (int c = 0; c < 24; c++) acc[c] = 0ULL;
#pragma unroll
    for (int sl = 0; sl < NSLOT; sl++) {
        float2 f = np[(size_t)sl * (D1CU/2)];
        ull m = pack2(f.x, f.y);
        int i = (sl % 9) % 3;
#pragma unroll
        for (int u = 0; u < 8; u++)
            ffma2(acc[u*3 + i], m, tw[sl*8 + u]);
    }
    float2* vp = (float2*)(g_v + (size_t)b*24*D1CU) + t2;
#pragma unroll
    for (int c = 0; c < 24; c++) {
        float2 f = unpack2(acc[c]);
        vp[(size_t)c * (D1CU/2)] = f;
    }
}

// ---------------- K3: basis conv2, kz-split, voxel-paired lanes ----------
// grid (4,4,BB*7); atomics into g_m[b][s=u*6+j][D2P]
__global__ __launch_bounds__(256, 3)
void k3_kernel() {
    extern __shared__ ull smu[];
    ull* sv  = smu;              // 3 * CSTU
    ull* smw = smu + 3*CSTU;     // K3W

    int tid = threadIdx.x;
    int kz = blockIdx.z % 7;
    int b  = blockIdx.z / 7;
    int ox0 = blockIdx.x * 5, oy0 = blockIdx.y * 5;

    int lx = tid % 5;
    int rr = tid / 5;
    int ly = rr % 5;
    int q10 = rr / 5;
    bool live = (q10 < 10);
    int q = live ? q10 : 0;

    for (int t = tid; t < K3W; t += 256) smw[t] = g_B2[kz*K3W + t];

    for (int u = 0; u < 8; u++) {
        __syncthreads();
        for (int c = 0; c < 3; c++) {
            const float* vp = g_v + ((size_t)b*24 + u*3 + c) * D1CU;
            for (int t = tid; t < 10*225; t += 256) {
                int xl = t % 15;
                int r2 = t / 15;
                int yl = r2 % 15;
                int p  = r2 / 15;
                int ix = 2*ox0 - 5 + xl;
                int iy = 2*oy0 - 5 + yl;
                int izA = 2*p + kz - 5;
                int izB = izA + 20;
                float a = 0.f, bb = 0.f;
                bool xy = ((unsigned)ix < D1 && (unsigned)iy < D1);
                if (xy && (unsigned)izA < D1) a  = vp[(size_t)izA*D1SQ + iy*D1 + ix];
                if (xy && (unsigned)izB < D1) bb = vp[(size_t)izB*D1SQ + iy*D1 + ix];
                sv[c*CSTU + p*PLNU + yl*15 + xl] = pack2(a, bb);
            }
        }
        __syncthreads();

        ull acc[6];
#pragma unroll
        for (int j = 0; j < 6; j++) acc[j] = 0ULL;

        const ull* p0 = &sv[q*PLNU + (2*ly)*15 + 2*lx];
#pragma unroll 1
        for (int ky = 0; ky < 7; ky++) {
#pragma unroll 1
            for (int kx = 0; kx < 7; kx++) {
                int off = ky*15 + kx;
                ull v0 = p0[off], v1 = p0[off + CSTU], v2 = p0[off + 2*CSTU];
                ull pr[6];
                pr[0] = mul2(v0, v0);
                pr[1] = mul2(v0, v1);
                pr[2] = mul2(v0, v2);
                pr[3] = mul2(v1, v1);
                pr[4] = mul2(v1, v2);
                pr[5] = mul2(v2, v2);
                const ull* w = &smw[(ky*7 + kx)*28];
                // a-part: interleave accs to avoid RAW chains
                ffma2(acc[0], v0, w[0]); ffma2(acc[1], v0, w[3]); ffma2(acc[2], v0, w[6]);
                ffma2(acc[0], v1, w[1]); ffma2(acc[1], v1, w[4]); ffma2(acc[2], v1, w[7]);
                ffma2(acc[0], v2, w[2]); ffma2(acc[1], v2, w[5]); ffma2(acc[2], v2, w[8]);
                // b-part
#pragma unroll
                for (int ic = 0; ic < 6; ic++) {
                    ffma2(acc[3], pr[ic], w[9  + ic]);
                    ffma2(acc[4], pr[ic], w[15 + ic]);
                    ffma2(acc[5], pr[ic], w[21 + ic]);
                }
            }
        }

        int ox = ox0 + lx, oy = oy0 + ly;
        if (live && ox < D2 && oy < D2) {
#pragma unroll
            for (int j = 0; j < 6; j++) {
                float2 f = unpack2(acc[j]);
                size_t base = ((size_t)b*MSLOT + u*6 + j)*D2P + oy*D2 + ox;
                atomicAdd(&g_m[base + (size_t)q*D2SQ], f.x);
                if (q < 9) atomicAdd(&g_m[base + (size_t)(q+10)*D2SQ], f.y);
            }
        }
    }
}

// ---------------- C2: combine m -> y + fused BN stats ----------------
__global__ void c2_kernel() {
    __shared__ ull tw[MSLOT*16];
    __shared__ float red[2*8*16];
    int tid = threadIdx.x;
    for (int t = tid; t < MSLOT*16; t += 256) tw[t] = g_W2s[t];
    __syncthreads();

    int idx = blockIdx.x * 256 + tid;          // pair index over BB*3430
    bool vt = (idx < BB*3430);
    int b  = vt ? idx / 3430 : 0;
    int t2 = vt ? idx % 3430 : 0;
    bool hasHi = vt && (2*t2 + 1 < D2CU);

    const float* mb = g_m + (size_t)b*MSLOT*D2P + 2*t2;
    ull acc[16];
#pragma unroll
    for (int c = 0; c < 16; c++) acc[c] = 0ULL;
#pragma unroll 4
    for (int s = 0; s < MSLOT; s++) {
        float2 f = *(const float2*)(mb + (size_t)s*D2P);
        ull m = pack2(f.x, f.y);
#pragma unroll
        for (int co = 0; co < 16; co++)
            ffma2(acc[co], m, tw[s*16 + co]);
    }

    float ylo[16], yhi[16];
#pragma unroll
    for (int co = 0; co < 16; co++) {
        float2 f = unpack2(acc[co]);
        ylo[co] = f.x; yhi[co] = f.y;
        if (vt) {
            size_t base = ((size_t)b*16 + co)*D2CU + 2*t2;
            g_y[base] = f.x;
            if (hasHi) g_y[base + 1] = f.y;
        }
    }

    int lane = tid & 31, wid = tid >> 5;
#pragma unroll
    for (int co = 0; co < 16; co++) {
        float s1 = 0.f, s2 = 0.f;
        if (vt)    { s1 += ylo[co]; s2 += ylo[co]*ylo[co]; }
        if (hasHi) { s1 += yhi[co]; s2 += yhi[co]*yhi[co]; }
#pragma unroll
        for (int o = 16; o > 0; o >>= 1) {
            s1 += __shfl_down_sync(0xffffffffu, s1, o);
            s2 += __shfl_down_sync(0xffffffffu, s2, o);
        }
        if (lane == 0) {
            red[wid*16 + co]       = s1;
            red[128 + wid*16 + co] = s2;
        }
    }
    __syncthreads();
    if (tid < 16) {
        float s1 = 0.f, s2 = 0.f;
#pragma unroll
        for (int w = 0; w < 8; w++) {
            s1 += red[w*16 + tid];
            s2 += red[128 + w*16 + tid];
        }
        atomicAdd(&g_sum[tid],   (double)s1);
        atomicAdd(&g_sumsq[tid], (double)s2);
    }
}

// ---------------- BN coefficients ----------------
__global__ void coef_kernel(const float* __restrict__ gamma,
                            const float* __restrict__ beta,
                            const float* __restrict__ bias) {
    int c = threadIdx.x;
    if (c < 16) {
        double N = (double)BB * (double)D2CU;
        double mean = g_sum[c] / N;
        double var  = g_sumsq[c] / N - mean*mean;
        float a = gamma[c] * rsqrtf((float)var + 1e-5f);
        g_coef[c]      = a;
        g_coef[16 + c] = beta[c] - a * (float)mean + bias[c];
    }
}

// ---------------- BN apply + bias + relu ----------------
__global__ void apply_kernel(float* __restrict__ out) {
    int idx = blockIdx.x * 256 + threadIdx.x;   // exactly Y_ELEMS
    int c = (idx / D2CU) & 15;
    float a = g_coef[c], b = g_coef[16 + c];
    out[idx] = fmaxf(fmaf(a, g_y[idx], b), 0.f);
}

// ---------------- launch ----------------
extern "C" void kernel_launch(void* const* d_in, const int* in_sizes, int n_in,
                              void* d_out, int out_size) {
    (void)in_sizes; (void)n_in; (void)out_size;
    const float* s       = (const float*)d_in[0];
    const float* basis1  = (const float*)d_in[1];
    const float* W1      = (const float*)d_in[2];
    const float* basis2a = (const float*)d_in[3];
    const float* basis2b = (const float*)d_in[4];
    const float* W2a     = (const float*)d_in[5];
    const float* W2b     = (const float*)d_in[6];
    const float* gamma   = (const float*)d_in[7];
    const float* beta    = (const float*)d_in[8];
    const float* bias    = (const float*)d_in[9];
    float* out = (float*)d_out;

    cudaFuncSetAttribute(k1_kernel,
        cudaFuncAttributeMaxDynamicSharedMemorySize, K1_SMEM);
    cudaFuncSetAttribute(k3_kernel,
        cudaFuncAttributeMaxDynamicSharedMemorySize, K3_SMEM);

    zero_m_kernel<<<M_ELEMS/256, 256>>>();
    gen_B1_kernel<<<(K1_W + 255)/256, 256>>>(basis1);
    gen_B2_kernel<<<(7*K3W + 255)/256, 256>>>(basis2a, basis2b);
    gen_W1s_kernel<<<2, 256>>>(W1);
    gen_W2s_kernel<<<3, 256>>>(W2a, W2b);
    k1_kernel<<<dim3(4, 4, BB*3), 256, K1_SMEM>>>(s);
    c1_kernel<<<(BB*(D1CU/2) + 255)/256, 256>>>();
    k3_kernel<<<dim3(4, 4, BB*7), 256, K3_SMEM>>>();
    c2_kernel<<<(BB*3430 + 255)/256, 256>>>();
    coef_kernel<<<1, 16>>>(gamma, beta, bias);
    apply_kernel<<<Y_ELEMS/256, 256>>>(out);
}